// round 4
// baseline (speedup 1.0000x reference)
#include <cuda_runtime.h>
#include <math.h>

#define PI_F 3.14159265358979323846

// One block = one 32x32 output tile. Stage the input bbox for ONE channel at
// a time into ~26KB smem (division-free, coalesced), bilinear-gather from smem.
// |c|+|s| == 1 exactly, so the bbox is always <= ~75 px per side for W=512,S=224.

constexpr int TILE  = 32;
constexpr int BLOCK = 512;   // 16 warps; 2 output pixels per thread
constexpr int MAXW  = 80;
constexpr int SMW   = 81;    // odd stride -> spread banks

__global__ void __launch_bounds__(BLOCK, 3) affine_tile_kernel(
    const float* __restrict__ x,      // [B, 3, H, W]
    const float* __restrict__ angles, // [B]
    float* __restrict__ out,          // [B, 3, S, S]
    int H, int W, int S, int ntx)
{
    __shared__ float sm[MAXW * SMW];  // 80*81*4 = 25,920 B

    const int b  = blockIdx.y;
    const int t  = blockIdx.x;
    const int tx = t % ntx;
    const int ty = t / ntx;
    const int ox0 = tx * TILE;
    const int oy0 = ty * TILE;

    // Rotation params (identical arithmetic to reference).
    const float rad = angles[b] * (float)(PI_F / 180.0);
    float sn, cs;
    sincosf(rad, &sn, &cs);
    const float scl = fabsf(cs) + fabsf(sn);
    const float c = cs / scl;
    const float s = sn / scl;
    const float stepx = 2.0f / (float)S;

    auto coord = [&](float oxf, float oyf, float& ix, float& iy) {
        float xs = (oxf + 0.5f) * stepx - 1.0f;
        float ys = (oyf + 0.5f) * stepx - 1.0f;
        float gx = c * xs - s * ys;
        float gy = s * xs + c * ys;
        ix = ((gx + 1.0f) * (float)W - 1.0f) * 0.5f;
        iy = ((gy + 1.0f) * (float)H - 1.0f) * 0.5f;
    };

    // Tile bbox from the 4 corners (ix,iy linear in ox,oy), + safety margin.
    float ixa, iya, ixb, iyb, ixc, iyc, ixd, iyd;
    coord((float)ox0,            (float)oy0,            ixa, iya);
    coord((float)(ox0 + TILE-1), (float)oy0,            ixb, iyb);
    coord((float)ox0,            (float)(oy0 + TILE-1), ixc, iyc);
    coord((float)(ox0 + TILE-1), (float)(oy0 + TILE-1), ixd, iyd);
    const float min_ix = fminf(fminf(ixa, ixb), fminf(ixc, ixd));
    const float max_ix = fmaxf(fmaxf(ixa, ixb), fmaxf(ixc, ixd));
    const float min_iy = fminf(fminf(iya, iyb), fminf(iyc, iyd));
    const float max_iy = fmaxf(fmaxf(iya, iyb), fmaxf(iyc, iyd));

    const int x_lo = max(0, (int)floorf(min_ix) - 1);
    const int x_hi = min(W - 1, (int)floorf(max_ix) + 2);
    const int y_lo = max(0, (int)floorf(min_iy) - 1);
    const int y_hi = min(H - 1, (int)floorf(max_iy) + 2);
    const int rw = x_hi - x_lo + 1;
    const int rh = y_hi - y_lo + 1;

    const bool fits = (rw <= MAXW) && (rh <= MAXW) && (rw > 0) && (rh > 0);

    const int tid  = threadIdx.x;
    const int lane = tid & 31;
    const int wid  = tid >> 5;          // 0..15
    const int oxl  = lane;              // 0..31
    const int oyl  = wid;               // 0..15 (second pixel at +16)

    const int ox = ox0 + oxl;
    const int oy_a = oy0 + oyl;
    const int oy_b = oy_a + 16;
    const bool va = (ox < S) && (oy_a < S);
    const bool vb = (ox < S) && (oy_b < S);

    // Cache the two sample coordinates in registers across the channel loop.
    float ixA, iyA, ixB, iyB;
    coord((float)ox, (float)oy_a, ixA, iyA);
    coord((float)ox, (float)oy_b, ixB, iyB);

    const long long HW = (long long)H * W;
    const long long SSo = (long long)S * S;

    if (fits) {
        #pragma unroll 1
        for (int ch = 0; ch < 3; ++ch) {
            if (ch > 0) __syncthreads();   // protect smem reuse

            // ---- stage bbox of this channel: warp-per-row, lane-strided ----
            const float* src = x + ((long long)(b * 3 + ch)) * HW
                                 + (long long)y_lo * W + x_lo;
            for (int r = wid; r < rh; r += 16) {
                const float* srow = src + (long long)r * W;
                float* drow = sm + r * SMW;
                for (int col = lane; col < rw; col += 32)
                    drow[col] = __ldg(srow + col);
            }
            __syncthreads();

            // ---- sample 2 pixels from smem ----
            float* obase = out + ((long long)(b * 3 + ch)) * SSo + ox;

            #pragma unroll
            for (int k = 0; k < 2; ++k) {
                const float ix = k ? ixB : ixA;
                const float iy = k ? iyB : iyA;
                const bool  v  = k ? vb : va;
                if (!v) continue;
                const int oy = k ? oy_b : oy_a;

                const float x0f = floorf(ix);
                const float y0f = floorf(iy);
                const int x0 = (int)x0f, y0 = (int)y0f;
                const int x1 = x0 + 1,  y1 = y0 + 1;

                const float wx1 = ix - x0f, wx0 = 1.0f - wx1;
                const float wy1 = iy - y0f, wy0 = 1.0f - wy1;

                const bool inx0 = (x0 >= 0) & (x0 < W);
                const bool inx1 = (x1 >= 0) & (x1 < W);
                const bool iny0 = (y0 >= 0) & (y0 < H);
                const bool iny1 = (y1 >= 0) & (y1 < H);

                const float w00 = (inx0 & iny0) ? (wy0 * wx0) : 0.0f;
                const float w01 = (inx1 & iny0) ? (wy0 * wx1) : 0.0f;
                const float w10 = (inx0 & iny1) ? (wy1 * wx0) : 0.0f;
                const float w11 = (inx1 & iny1) ? (wy1 * wx1) : 0.0f;

                const int x0l = min(max(x0, 0), W - 1) - x_lo;
                const int x1l = min(max(x1, 0), W - 1) - x_lo;
                const int y0l = min(max(y0, 0), H - 1) - y_lo;
                const int y1l = min(max(y1, 0), H - 1) - y_lo;

                const float* r0 = sm + y0l * SMW;
                const float* r1 = sm + y1l * SMW;
                float v0 = w00 * r0[x0l] + w01 * r0[x1l]
                         + w10 * r1[x0l] + w11 * r1[x1l];
                obase[(long long)oy * S] = v0;
            }
        }
    } else {
        // Fallback: direct global gather (block-uniform branch).
        const float* img = x + (long long)b * 3 * HW;
        #pragma unroll
        for (int k = 0; k < 2; ++k) {
            const float ix = k ? ixB : ixA;
            const float iy = k ? iyB : iyA;
            const bool  v  = k ? vb : va;
            if (!v) continue;
            const int oy = k ? oy_b : oy_a;

            const float x0f = floorf(ix);
            const float y0f = floorf(iy);
            const int x0 = (int)x0f, y0 = (int)y0f;
            const int x1 = x0 + 1,  y1 = y0 + 1;

            const float wx1 = ix - x0f, wx0 = 1.0f - wx1;
            const float wy1 = iy - y0f, wy0 = 1.0f - wy1;

            const bool inx0 = (x0 >= 0) & (x0 < W);
            const bool inx1 = (x1 >= 0) & (x1 < W);
            const bool iny0 = (y0 >= 0) & (y0 < H);
            const bool iny1 = (y1 >= 0) & (y1 < H);

            const float w00 = (inx0 & iny0) ? (wy0 * wx0) : 0.0f;
            const float w01 = (inx1 & iny0) ? (wy0 * wx1) : 0.0f;
            const float w10 = (inx0 & iny1) ? (wy1 * wx0) : 0.0f;
            const float w11 = (inx1 & iny1) ? (wy1 * wx1) : 0.0f;

            const long long i00 = (long long)min(max(y0,0),H-1) * W + min(max(x0,0),W-1);
            const long long i01 = (long long)min(max(y0,0),H-1) * W + min(max(x1,0),W-1);
            const long long i10 = (long long)min(max(y1,0),H-1) * W + min(max(x0,0),W-1);
            const long long i11 = (long long)min(max(y1,0),H-1) * W + min(max(x1,0),W-1);

            #pragma unroll
            for (int ch = 0; ch < 3; ++ch) {
                const float* p = img + (long long)ch * HW;
                float vv = w00 * __ldg(p + i00) + w01 * __ldg(p + i01)
                         + w10 * __ldg(p + i10) + w11 * __ldg(p + i11);
                out[((long long)(b * 3 + ch)) * SSo + (long long)oy * S + ox] = vv;
            }
        }
    }
}

extern "C" void kernel_launch(void* const* d_in, const int* in_sizes, int n_in,
                              void* d_out, int out_size)
{
    const float* x = (const float*)d_in[0];
    const float* angles = (const float*)d_in[1];
    float* out = (float*)d_out;

    const int B = in_sizes[1];
    const int C = 3;
    const long long hw = (long long)in_sizes[0] / ((long long)B * C);
    const int H = (int)(sqrt((double)hw) + 0.5);
    const int W = H;
    const long long ss = (long long)out_size / ((long long)B * C);
    const int S = (int)(sqrt((double)ss) + 0.5);

    const int ntx = (S + TILE - 1) / TILE;
    const int nty = (S + TILE - 1) / TILE;

    dim3 grid(ntx * nty, B, 1);
    affine_tile_kernel<<<grid, BLOCK>>>(x, angles, out, H, W, S, ntx);
}

// round 6
// speedup vs baseline: 1.0002x; 1.0002x over previous
#include <cuda_runtime.h>
#include <math.h>

#define PI_F 3.14159265358979323846

// One block = one 32x32 output tile. Stage the input bbox for ONE channel at
// a time into ~26KB smem (division-free, coalesced), bilinear-gather from smem.
// |c|+|s| == 1 exactly, so the bbox is always <= ~75 px per side for W=512,S=224.

constexpr int TILE  = 32;
constexpr int BLOCK = 512;   // 16 warps; 2 output pixels per thread
constexpr int MAXW  = 80;
constexpr int SMW   = 81;    // odd stride -> spread banks

__global__ void __launch_bounds__(BLOCK, 3) affine_tile_kernel(
    const float* __restrict__ x,      // [B, 3, H, W]
    const float* __restrict__ angles, // [B]
    float* __restrict__ out,          // [B, 3, S, S]
    int H, int W, int S, int ntx)
{
    __shared__ float sm[MAXW * SMW];  // 80*81*4 = 25,920 B

    const int b  = blockIdx.y;
    const int t  = blockIdx.x;
    const int tx = t % ntx;
    const int ty = t / ntx;
    const int ox0 = tx * TILE;
    const int oy0 = ty * TILE;

    // Rotation params (identical arithmetic to reference).
    const float rad = angles[b] * (float)(PI_F / 180.0);
    float sn, cs;
    sincosf(rad, &sn, &cs);
    const float scl = fabsf(cs) + fabsf(sn);
    const float c = cs / scl;
    const float s = sn / scl;
    const float stepx = 2.0f / (float)S;

    auto coord = [&](float oxf, float oyf, float& ix, float& iy) {
        float xs = (oxf + 0.5f) * stepx - 1.0f;
        float ys = (oyf + 0.5f) * stepx - 1.0f;
        float gx = c * xs - s * ys;
        float gy = s * xs + c * ys;
        ix = ((gx + 1.0f) * (float)W - 1.0f) * 0.5f;
        iy = ((gy + 1.0f) * (float)H - 1.0f) * 0.5f;
    };

    // Tile bbox from the 4 corners (ix,iy linear in ox,oy), + safety margin.
    float ixa, iya, ixb, iyb, ixc, iyc, ixd, iyd;
    coord((float)ox0,            (float)oy0,            ixa, iya);
    coord((float)(ox0 + TILE-1), (float)oy0,            ixb, iyb);
    coord((float)ox0,            (float)(oy0 + TILE-1), ixc, iyc);
    coord((float)(ox0 + TILE-1), (float)(oy0 + TILE-1), ixd, iyd);
    const float min_ix = fminf(fminf(ixa, ixb), fminf(ixc, ixd));
    const float max_ix = fmaxf(fmaxf(ixa, ixb), fmaxf(ixc, ixd));
    const float min_iy = fminf(fminf(iya, iyb), fminf(iyc, iyd));
    const float max_iy = fmaxf(fmaxf(iya, iyb), fmaxf(iyc, iyd));

    const int x_lo = max(0, (int)floorf(min_ix) - 1);
    const int x_hi = min(W - 1, (int)floorf(max_ix) + 2);
    const int y_lo = max(0, (int)floorf(min_iy) - 1);
    const int y_hi = min(H - 1, (int)floorf(max_iy) + 2);
    const int rw = x_hi - x_lo + 1;
    const int rh = y_hi - y_lo + 1;

    const bool fits = (rw <= MAXW) && (rh <= MAXW) && (rw > 0) && (rh > 0);

    const int tid  = threadIdx.x;
    const int lane = tid & 31;
    const int wid  = tid >> 5;          // 0..15

    const int ox = ox0 + lane;
    const int oy_a = oy0 + wid;
    const int oy_b = oy_a + 16;
    const bool va = (ox < S) && (oy_a < S);
    const bool vb = (ox < S) && (oy_b < S);

    // Cache the two sample coordinates in registers across the channel loop.
    float ixA, iyA, ixB, iyB;
    coord((float)ox, (float)oy_a, ixA, iyA);
    coord((float)ox, (float)oy_b, ixB, iyB);

    const long long HW = (long long)H * W;
    const long long SSo = (long long)S * S;

    if (fits) {
        #pragma unroll 1
        for (int ch = 0; ch < 3; ++ch) {
            if (ch > 0) __syncthreads();   // protect smem reuse

            // ---- stage bbox of this channel: warp-per-row, lane-strided ----
            const float* src = x + ((long long)(b * 3 + ch)) * HW
                                 + (long long)y_lo * W + x_lo;
            for (int r = wid; r < rh; r += 16) {
                const float* srow = src + (long long)r * W;
                float* drow = sm + r * SMW;
                for (int col = lane; col < rw; col += 32)
                    drow[col] = __ldg(srow + col);
            }
            __syncthreads();

            // ---- sample 2 pixels from smem ----
            float* obase = out + ((long long)(b * 3 + ch)) * SSo + ox;

            #pragma unroll
            for (int k = 0; k < 2; ++k) {
                const float ix = k ? ixB : ixA;
                const float iy = k ? iyB : iyA;
                const bool  v  = k ? vb : va;
                if (!v) continue;
                const int oy = k ? oy_b : oy_a;

                const float x0f = floorf(ix);
                const float y0f = floorf(iy);
                const int x0 = (int)x0f, y0 = (int)y0f;
                const int x1 = x0 + 1,  y1 = y0 + 1;

                const float wx1 = ix - x0f, wx0 = 1.0f - wx1;
                const float wy1 = iy - y0f, wy0 = 1.0f - wy1;

                const bool inx0 = (x0 >= 0) & (x0 < W);
                const bool inx1 = (x1 >= 0) & (x1 < W);
                const bool iny0 = (y0 >= 0) & (y0 < H);
                const bool iny1 = (y1 >= 0) & (y1 < H);

                const float w00 = (inx0 & iny0) ? (wy0 * wx0) : 0.0f;
                const float w01 = (inx1 & iny0) ? (wy0 * wx1) : 0.0f;
                const float w10 = (inx0 & iny1) ? (wy1 * wx0) : 0.0f;
                const float w11 = (inx1 & iny1) ? (wy1 * wx1) : 0.0f;

                const int x0l = min(max(x0, 0), W - 1) - x_lo;
                const int x1l = min(max(x1, 0), W - 1) - x_lo;
                const int y0l = min(max(y0, 0), H - 1) - y_lo;
                const int y1l = min(max(y1, 0), H - 1) - y_lo;

                const float* r0 = sm + y0l * SMW;
                const float* r1 = sm + y1l * SMW;
                float v0 = w00 * r0[x0l] + w01 * r0[x1l]
                         + w10 * r1[x0l] + w11 * r1[x1l];
                obase[(long long)oy * S] = v0;
            }
        }
    } else {
        // Fallback: direct global gather (block-uniform branch).
        const float* img = x + (long long)b * 3 * HW;
        #pragma unroll
        for (int k = 0; k < 2; ++k) {
            const float ix = k ? ixB : ixA;
            const float iy = k ? iyB : iyA;
            const bool  v  = k ? vb : va;
            if (!v) continue;
            const int oy = k ? oy_b : oy_a;

            const float x0f = floorf(ix);
            const float y0f = floorf(iy);
            const int x0 = (int)x0f, y0 = (int)y0f;
            const int x1 = x0 + 1,  y1 = y0 + 1;

            const float wx1 = ix - x0f, wx0 = 1.0f - wx1;
            const float wy1 = iy - y0f, wy0 = 1.0f - wy1;

            const bool inx0 = (x0 >= 0) & (x0 < W);
            const bool inx1 = (x1 >= 0) & (x1 < W);
            const bool iny0 = (y0 >= 0) & (y0 < H);
            const bool iny1 = (y1 >= 0) & (y1 < H);

            const float w00 = (inx0 & iny0) ? (wy0 * wx0) : 0.0f;
            const float w01 = (inx1 & iny0) ? (wy0 * wx1) : 0.0f;
            const float w10 = (inx0 & iny1) ? (wy1 * wx0) : 0.0f;
            const float w11 = (inx1 & iny1) ? (wy1 * wx1) : 0.0f;

            const long long i00 = (long long)min(max(y0,0),H-1) * W + min(max(x0,0),W-1);
            const long long i01 = (long long)min(max(y0,0),H-1) * W + min(max(x1,0),W-1);
            const long long i10 = (long long)min(max(y1,0),H-1) * W + min(max(x0,0),W-1);
            const long long i11 = (long long)min(max(y1,0),H-1) * W + min(max(x1,0),W-1);

            #pragma unroll
            for (int ch = 0; ch < 3; ++ch) {
                const float* p = img + (long long)ch * HW;
                float vv = w00 * __ldg(p + i00) + w01 * __ldg(p + i01)
                         + w10 * __ldg(p + i10) + w11 * __ldg(p + i11);
                out[((long long)(b * 3 + ch)) * SSo + (long long)oy * S + ox] = vv;
            }
        }
    }
}

extern "C" void kernel_launch(void* const* d_in, const int* in_sizes, int n_in,
                              void* d_out, int out_size)
{
    const float* x = (const float*)d_in[0];
    const float* angles = (const float*)d_in[1];
    float* out = (float*)d_out;

    const int B = in_sizes[1];
    const int C = 3;
    const long long hw = (long long)in_sizes[0] / ((long long)B * C);
    const int H = (int)(sqrt((double)hw) + 0.5);
    const int W = H;
    const long long ss = (long long)out_size / ((long long)B * C);
    const int S = (int)(sqrt((double)ss) + 0.5);

    const int ntx = (S + TILE - 1) / TILE;
    const int nty = (S + TILE - 1) / TILE;

    dim3 grid(ntx * nty, B, 1);
    affine_tile_kernel<<<grid, BLOCK>>>(x, angles, out, H, W, S, ntx);
}

// round 10
// speedup vs baseline: 1.9710x; 1.9705x over previous
#include <cuda_runtime.h>
#include <cstdint>
#include <math.h>

#define PI_F 3.14159265358979323846

// One block = one 32x32 output tile. Double-buffered cp.async staging of the
// (always) 80x80 input box per channel, pipelined across the 3 channels,
// bilinear gather from smem. |c|+|s| == 1 exactly -> bbox <= ~75 px/side.
// Double buffer = 51.8KB -> dynamic smem (static is capped at 48KB).

constexpr int TILE  = 32;
constexpr int BLOCK = 512;     // 16 warps
constexpr int MAXW  = 80;
constexpr int SMW   = 81;      // padded smem row stride
constexpr int BUFN  = MAXW * SMW;

__device__ __forceinline__ void cp4(unsigned int dst, const float* src) {
    asm volatile("cp.async.ca.shared.global [%0], [%1], 4;" :: "r"(dst), "l"(src));
}
__device__ __forceinline__ void cp_commit() {
    asm volatile("cp.async.commit_group;");
}
template <int N> __device__ __forceinline__ void cp_wait() {
    asm volatile("cp.async.wait_group %0;" :: "n"(N));
}

// Stage the 80x80 box of one channel into smem buffer (u32 addr).
// Fixed trip counts -> fully unrolled, 15 independent LDGSTS per thread.
__device__ __forceinline__ void stage_box(
    const float* __restrict__ chan, int y_lo, int x_lo, int H, int W,
    unsigned int sbuf, int wid, int lane)
{
    #pragma unroll
    for (int rr = 0; rr < 5; ++rr) {
        const int r  = wid + rr * 16;                    // 0..79
        const int yr = min(y_lo + r, H - 1);             // y_lo >= 0
        const float* srow = chan + (long long)yr * W;
        #pragma unroll
        for (int cc = 0; cc < 3; ++cc) {
            const int col = lane + cc * 32;              // 0..95
            if (cc < 2 || lane < MAXW - 64) {            // col < 80
                const int xc = min(x_lo + col, W - 1);   // x_lo >= 0
                cp4(sbuf + (unsigned int)(r * SMW + col) * 4u, srow + xc);
            }
        }
    }
}

__global__ void __launch_bounds__(BLOCK, 2) affine_tile_kernel(
    const float* __restrict__ x,      // [B, 3, H, W]
    const float* __restrict__ angles, // [B]
    float* __restrict__ out,          // [B, 3, S, S]
    int H, int W, int S, int ntx)
{
    extern __shared__ float sm[];     // 2 x BUFN floats (51,840 B)

    const int b  = blockIdx.y;
    const int t  = blockIdx.x;
    const int tx = t % ntx;
    const int ty = t / ntx;
    const int ox0 = tx * TILE;
    const int oy0 = ty * TILE;

    // Rotation params (identical arithmetic to reference).
    const float rad = angles[b] * (float)(PI_F / 180.0);
    float sn, cs;
    sincosf(rad, &sn, &cs);
    const float scl = fabsf(cs) + fabsf(sn);
    const float c = cs / scl;
    const float s = sn / scl;
    const float stepx = 2.0f / (float)S;

    auto coord = [&](float oxf, float oyf, float& ix, float& iy) {
        float xs = (oxf + 0.5f) * stepx - 1.0f;
        float ys = (oyf + 0.5f) * stepx - 1.0f;
        float gx = c * xs - s * ys;
        float gy = s * xs + c * ys;
        ix = ((gx + 1.0f) * (float)W - 1.0f) * 0.5f;
        iy = ((gy + 1.0f) * (float)H - 1.0f) * 0.5f;
    };

    // Tile bbox from the 4 corners (ix,iy linear in ox,oy), + safety margin.
    float ixa, iya, ixb, iyb, ixc, iyc, ixd, iyd;
    coord((float)ox0,            (float)oy0,            ixa, iya);
    coord((float)(ox0 + TILE-1), (float)oy0,            ixb, iyb);
    coord((float)ox0,            (float)(oy0 + TILE-1), ixc, iyc);
    coord((float)(ox0 + TILE-1), (float)(oy0 + TILE-1), ixd, iyd);
    const float min_ix = fminf(fminf(ixa, ixb), fminf(ixc, ixd));
    const float max_ix = fmaxf(fmaxf(ixa, ixb), fmaxf(ixc, ixd));
    const float min_iy = fminf(fminf(iya, iyb), fminf(iyc, iyd));
    const float max_iy = fmaxf(fmaxf(iya, iyb), fmaxf(iyc, iyd));

    const int x_lo = max(0, (int)floorf(min_ix) - 1);
    const int x_hi = min(W - 1, (int)floorf(max_ix) + 2);
    const int y_lo = max(0, (int)floorf(min_iy) - 1);
    const int y_hi = min(H - 1, (int)floorf(max_iy) + 2);
    const int rw = x_hi - x_lo + 1;
    const int rh = y_hi - y_lo + 1;
    const bool fits = (rw <= MAXW) && (rh <= MAXW) && (rw > 0) && (rh > 0);

    const int tid  = threadIdx.x;
    const int lane = tid & 31;
    const int wid  = tid >> 5;          // 0..15

    const long long HW  = (long long)H * W;
    const long long SSo = (long long)S * S;
    const float* chan0 = x + (long long)(b * 3) * HW;

    unsigned int s0 = (unsigned int)__cvta_generic_to_shared(&sm[0]);
    unsigned int s1 = (unsigned int)__cvta_generic_to_shared(&sm[BUFN]);

    if (fits) {
        // Kick off channel 0 and 1 staging immediately (deep prefetch).
        stage_box(chan0,          y_lo, x_lo, H, W, s0, wid, lane);
        cp_commit();
        stage_box(chan0 + HW,     y_lo, x_lo, H, W, s1, wid, lane);
        cp_commit();
    }

    // ---- per-thread sample coords & masked weights (computed while copies fly) ----
    const int ox   = ox0 + lane;
    const int oy_a = oy0 + wid;
    const int oy_b = oy_a + 16;
    const bool vA = (ox < S) && (oy_a < S);
    const bool vB = (ox < S) && (oy_b < S);

    float wx0m[2], wx1m[2], wy0m[2], wy1m[2];
    int   xl0[2], xl1[2], ro0[2], ro1[2];

    #pragma unroll
    for (int k = 0; k < 2; ++k) {
        float ix, iy;
        coord((float)ox, (float)(k ? oy_b : oy_a), ix, iy);

        const float x0f = floorf(ix);
        const float y0f = floorf(iy);
        const int x0 = (int)x0f, y0 = (int)y0f;
        const int x1 = x0 + 1,  y1 = y0 + 1;

        const float wx1 = ix - x0f, wx0 = 1.0f - wx1;
        const float wy1 = iy - y0f, wy0 = 1.0f - wy1;

        wx0m[k] = ((x0 >= 0) & (x0 < W)) ? wx0 : 0.0f;
        wx1m[k] = ((x1 >= 0) & (x1 < W)) ? wx1 : 0.0f;
        wy0m[k] = ((y0 >= 0) & (y0 < H)) ? wy0 : 0.0f;
        wy1m[k] = ((y1 >= 0) & (y1 < H)) ? wy1 : 0.0f;

        xl0[k] = min(max(x0, 0), W - 1) - x_lo;
        xl1[k] = min(max(x1, 0), W - 1) - x_lo;
        ro0[k] = (min(max(y0, 0), H - 1) - y_lo) * SMW;
        ro1[k] = (min(max(y1, 0), H - 1) - y_lo) * SMW;
    }

    if (fits) {
        auto gather = [&](const float* buf, int ch) {
            float* ob = out + ((long long)(b * 3 + ch)) * SSo + ox;
            #pragma unroll
            for (int k = 0; k < 2; ++k) {
                const bool v = k ? vB : vA;
                if (!v) continue;
                const int oy = k ? oy_b : oy_a;
                const float* r0 = buf + ro0[k];
                const float* r1 = buf + ro1[k];
                float acc = (wy0m[k] * wx0m[k]) * r0[xl0[k]]
                          + (wy0m[k] * wx1m[k]) * r0[xl1[k]]
                          + (wy1m[k] * wx0m[k]) * r1[xl0[k]]
                          + (wy1m[k] * wx1m[k]) * r1[xl1[k]];
                ob[(long long)oy * S] = acc;
            }
        };

        // ch 0 (groups pending: G0, G1 -> wait until <=1 left = G0 done)
        cp_wait<1>();
        __syncthreads();
        gather(sm, 0);
        __syncthreads();

        // prefetch ch2 into buffer 0 (safe: all reads of sm[0..] done)
        stage_box(chan0 + 2 * HW, y_lo, x_lo, H, W, s0, wid, lane);
        cp_commit();

        // ch 1 (pending G1, G2 -> wait until <=1 = G1 done)
        cp_wait<1>();
        __syncthreads();
        gather(sm + BUFN, 1);
        __syncthreads();

        // ch 2
        cp_wait<0>();
        __syncthreads();
        gather(sm, 2);
    } else {
        // Fallback: direct global gather (block-uniform branch).
        #pragma unroll
        for (int k = 0; k < 2; ++k) {
            const bool v = k ? vB : vA;
            if (!v) continue;
            const int oy = k ? oy_b : oy_a;
            // Recover global indices from the local ones.
            const long long i00 = (long long)(ro0[k] / SMW + y_lo) * W + (xl0[k] + x_lo);
            const long long i01 = (long long)(ro0[k] / SMW + y_lo) * W + (xl1[k] + x_lo);
            const long long i10 = (long long)(ro1[k] / SMW + y_lo) * W + (xl0[k] + x_lo);
            const long long i11 = (long long)(ro1[k] / SMW + y_lo) * W + (xl1[k] + x_lo);
            #pragma unroll
            for (int ch = 0; ch < 3; ++ch) {
                const float* p = chan0 + (long long)ch * HW;
                float acc = (wy0m[k] * wx0m[k]) * __ldg(p + i00)
                          + (wy0m[k] * wx1m[k]) * __ldg(p + i01)
                          + (wy1m[k] * wx0m[k]) * __ldg(p + i10)
                          + (wy1m[k] * wx1m[k]) * __ldg(p + i11);
                out[((long long)(b * 3 + ch)) * SSo + (long long)oy * S + ox] = acc;
            }
        }
    }
}

extern "C" void kernel_launch(void* const* d_in, const int* in_sizes, int n_in,
                              void* d_out, int out_size)
{
    const float* x = (const float*)d_in[0];
    const float* angles = (const float*)d_in[1];
    float* out = (float*)d_out;

    const int B = in_sizes[1];
    const int C = 3;
    const long long hw = (long long)in_sizes[0] / ((long long)B * C);
    const int H = (int)(sqrt((double)hw) + 0.5);
    const int W = H;
    const long long ss = (long long)out_size / ((long long)B * C);
    const int S = (int)(sqrt((double)ss) + 0.5);

    const int ntx = (S + TILE - 1) / TILE;
    const int nty = (S + TILE - 1) / TILE;

    const size_t smem = 2 * BUFN * sizeof(float);   // 51,840 B
    cudaFuncSetAttribute(affine_tile_kernel,
                         cudaFuncAttributeMaxDynamicSharedMemorySize, (int)smem);

    dim3 grid(ntx * nty, B, 1);
    affine_tile_kernel<<<grid, BLOCK, smem>>>(x, angles, out, H, W, S, ntx);
}

// round 11
// speedup vs baseline: 3.0068x; 1.5255x over previous
#include <cuda_runtime.h>
#include <math.h>

#define PI_F 3.14159265358979323846

// Direct bilinear gather, warp-tiled for L1 locality:
// each warp covers an 8x4 output pixel tile (lanes: 8 wide x 4 tall), so its
// input-space gather footprint is ~13x13 px even at 45 deg, instead of the
// 32x1 mapping whose footprint spans up to ~73 input rows (L1 replay storm).
// Block = 256 threads = 8 warps arranged 4x2 -> covers a 32x8 output region.
// One thread does all 3 channels (coords/weights computed once).

constexpr int BLOCK = 256;

__global__ void __launch_bounds__(BLOCK) affine_warp_tile_kernel(
    const float* __restrict__ x,      // [B, 3, H, W]
    const float* __restrict__ angles, // [B]
    float* __restrict__ out,          // [B, 3, S, S]
    int H, int W, int S, int ntx)
{
    const int b = blockIdx.y;
    const int t = blockIdx.x;
    const int tx = t % ntx;           // 32-wide tiles across
    const int ty = t / ntx;           // 8-tall tiles down

    const int tid  = threadIdx.x;
    const int lane = tid & 31;
    const int w    = tid >> 5;        // warp 0..7

    // warp position inside the 32x8 block region: 4 across x, 2 down y
    const int ox = tx * 32 + (w & 3) * 8 + (lane & 7);
    const int oy = ty * 8  + (w >> 2) * 4 + (lane >> 3);

    if (ox >= S || oy >= S) return;

    // Rotation params (identical arithmetic to the reference).
    const float rad = angles[b] * (float)(PI_F / 180.0);
    float sn, cs;
    sincosf(rad, &sn, &cs);
    const float scl = fabsf(cs) + fabsf(sn);
    const float c = cs / scl;
    const float s = sn / scl;

    const float step = 2.0f / (float)S;
    const float xs = ((float)ox + 0.5f) * step - 1.0f;
    const float ys = ((float)oy + 0.5f) * step - 1.0f;

    const float gx = c * xs - s * ys;
    const float gy = s * xs + c * ys;

    const float ix = ((gx + 1.0f) * (float)W - 1.0f) * 0.5f;
    const float iy = ((gy + 1.0f) * (float)H - 1.0f) * 0.5f;

    const float x0f = floorf(ix);
    const float y0f = floorf(iy);
    const int x0 = (int)x0f;
    const int y0 = (int)y0f;
    const int x1 = x0 + 1;
    const int y1 = y0 + 1;

    const float wx1 = ix - x0f;
    const float wx0 = 1.0f - wx1;
    const float wy1 = iy - y0f;
    const float wy0 = 1.0f - wy1;

    const bool inx0 = (x0 >= 0) & (x0 < W);
    const bool inx1 = (x1 >= 0) & (x1 < W);
    const bool iny0 = (y0 >= 0) & (y0 < H);
    const bool iny1 = (y1 >= 0) & (y1 < H);

    // Fold zero-padding masks into the bilinear weights (branchless).
    const float w00 = (inx0 & iny0) ? (wy0 * wx0) : 0.0f;
    const float w01 = (inx1 & iny0) ? (wy0 * wx1) : 0.0f;
    const float w10 = (inx0 & iny1) ? (wy1 * wx0) : 0.0f;
    const float w11 = (inx1 & iny1) ? (wy1 * wx1) : 0.0f;

    const int x0c = min(max(x0, 0), W - 1);
    const int x1c = min(max(x1, 0), W - 1);
    const int y0c = min(max(y0, 0), H - 1);
    const int y1c = min(max(y1, 0), H - 1);

    const long long i00 = (long long)y0c * W + x0c;
    const long long i01 = (long long)y0c * W + x1c;
    const long long i10 = (long long)y1c * W + x0c;
    const long long i11 = (long long)y1c * W + x1c;

    const long long HW  = (long long)H * W;
    const long long SSo = (long long)S * S;
    const float* img = x + (long long)b * 3 * HW;
    float* obase = out + (long long)b * 3 * SSo + (long long)oy * S + ox;

    #pragma unroll 3
    for (int ch = 0; ch < 3; ++ch) {
        const float* p = img + (long long)ch * HW;
        float v = w00 * __ldg(p + i00)
                + w01 * __ldg(p + i01)
                + w10 * __ldg(p + i10)
                + w11 * __ldg(p + i11);
        obase[(long long)ch * SSo] = v;
    }
}

extern "C" void kernel_launch(void* const* d_in, const int* in_sizes, int n_in,
                              void* d_out, int out_size)
{
    const float* x = (const float*)d_in[0];
    const float* angles = (const float*)d_in[1];
    float* out = (float*)d_out;

    const int B = in_sizes[1];
    const int C = 3;
    const long long hw = (long long)in_sizes[0] / ((long long)B * C);
    const int H = (int)(sqrt((double)hw) + 0.5);
    const int W = H;
    const long long ss = (long long)out_size / ((long long)B * C);
    const int S = (int)(sqrt((double)ss) + 0.5);

    const int ntx = (S + 31) / 32;    // 32-wide block regions
    const int nty = (S + 7) / 8;      // 8-tall block regions

    dim3 grid(ntx * nty, B, 1);
    affine_warp_tile_kernel<<<grid, BLOCK>>>(x, angles, out, H, W, S, ntx);
}